// round 12
// baseline (speedup 1.0000x reference)
#include <cuda_runtime.h>
#include <cstdint>

#define D_IN   768
#define D_SAE  12288
#define T_LEN  64
#define KTOP   64
#define BATCH  32
#define NROWS  (BATCH * T_LEN)   // 2048

// ---------------- scratch (static device globals; no allocations) ----------------
__device__ __align__(16) float g_pre[(size_t)NROWS * D_SAE];     // 96 MB (exact fp32)
__device__ int   g_topidx[NROWS * 128];   // SORTED by composite desc
__device__ float g_topval[NROWS * 128];
__device__ int   g_zidx[NROWS * KTOP];
__device__ float g_zval[NROWS * KTOP];
__device__ float g_rowloss[NROWS];

// ---------------- helpers ----------------
__device__ __forceinline__ unsigned long long pack2(float x, float y) {
    unsigned long long r;
    asm("mov.b64 %0, {%1, %2};" : "=l"(r) : "f"(x), "f"(y));
    return r;
}
__device__ __forceinline__ float2 unpack2(unsigned long long v) {
    float2 f;
    asm("mov.b64 {%0, %1}, %2;" : "=f"(f.x), "=f"(f.y) : "l"(v));
    return f;
}
__device__ __forceinline__ void fma2(unsigned long long& c, unsigned long long a, unsigned long long b) {
    asm("fma.rn.f32x2 %0, %1, %2, %0;" : "+l"(c) : "l"(a), "l"(b));
}
__device__ __forceinline__ unsigned int fkey(float v) {
    unsigned int u = __float_as_uint(v);
    return (u & 0x80000000u) ? ~u : (u | 0x80000000u);
}
__device__ __forceinline__ float keyToFloat(unsigned int k) {
    unsigned int u = (k & 0x80000000u) ? (k & 0x7FFFFFFFu) : ~k;
    return __uint_as_float(u);
}
// larger == (greater value) or (equal value, smaller index)  [jax top_k tie rule]
__device__ __forceinline__ unsigned long long makeComp(float v, int idx) {
    return ((unsigned long long)fkey(v) << 32) | (unsigned long long)(0xFFFFFFFFu - (unsigned int)idx);
}
__device__ __forceinline__ float sigmoidf(float x) {
    return 1.0f / (1.0f + expf(-x));
}

// ======================================================================
// Kernel A: fp32 GEMM (proven variant; at the FFMA2 rt=3 roofline).
// ======================================================================
__global__ __launch_bounds__(256, 1) void gemm_enc(const float* __restrict__ X,
                                                   const float* __restrict__ W,
                                                   const float* __restrict__ bias) {
    __shared__ __align__(16) float As[2][16][128];
    __shared__ __align__(16) float Bs[2][16][128];

    const int tid  = threadIdx.x;
    const int row0 = blockIdx.y * 128;
    const int col0 = blockIdx.x * 128;
    const int tx = tid & 15, ty = tid >> 4;

    const int aRow = tid >> 2;
    const int aCol = (tid & 3) * 4;
    const int bRow = tid >> 5;
    const int bCol = (tid & 31) * 4;

    const float* Aptr = X + (size_t)row0 * D_IN;
    const float* Bptr = W + col0;

    float4 a0, a1, b0, b1;
    a0 = *(const float4*)(Aptr + (size_t)aRow * D_IN + aCol);
    a1 = *(const float4*)(Aptr + (size_t)(aRow + 64) * D_IN + aCol);
    b0 = *(const float4*)(Bptr + (size_t)bRow * D_SAE + bCol);
    b1 = *(const float4*)(Bptr + (size_t)(bRow + 8) * D_SAE + bCol);
    As[0][aCol + 0][aRow] = a0.x; As[0][aCol + 1][aRow] = a0.y;
    As[0][aCol + 2][aRow] = a0.z; As[0][aCol + 3][aRow] = a0.w;
    As[0][aCol + 0][aRow + 64] = a1.x; As[0][aCol + 1][aRow + 64] = a1.y;
    As[0][aCol + 2][aRow + 64] = a1.z; As[0][aCol + 3][aRow + 64] = a1.w;
    *(float4*)&Bs[0][bRow][bCol]     = b0;
    *(float4*)&Bs[0][bRow + 8][bCol] = b1;
    __syncthreads();

    unsigned long long cc[4][8];
#pragma unroll
    for (int i = 0; i < 4; ++i)
#pragma unroll
        for (int j = 0; j < 8; ++j) cc[i][j] = 0ull;

    const int NKT = D_IN / 16;  // 48
    for (int kt = 0; kt < NKT; ++kt) {
        const int cur = kt & 1;
        if (kt < NKT - 1) {
            const int k0 = (kt + 1) * 16;
            a0 = *(const float4*)(Aptr + (size_t)aRow * D_IN + k0 + aCol);
            a1 = *(const float4*)(Aptr + (size_t)(aRow + 64) * D_IN + k0 + aCol);
            b0 = *(const float4*)(Bptr + (size_t)(k0 + bRow) * D_SAE + bCol);
            b1 = *(const float4*)(Bptr + (size_t)(k0 + bRow + 8) * D_SAE + bCol);
        }
#pragma unroll
        for (int k = 0; k < 16; ++k) {
            ulonglong2 aa01 = *(const ulonglong2*)&As[cur][k][ty * 4];
            ulonglong2 aa23 = *(const ulonglong2*)&As[cur][k][64 + ty * 4];
            float4 bv0 = *(const float4*)&Bs[cur][k][tx * 4];
            float4 bv1 = *(const float4*)&Bs[cur][k][64 + tx * 4];
            unsigned long long av[4] = {aa01.x, aa01.y, aa23.x, aa23.y};
            unsigned long long bb[8] = {pack2(bv0.x, bv0.x), pack2(bv0.y, bv0.y),
                                        pack2(bv0.z, bv0.z), pack2(bv0.w, bv0.w),
                                        pack2(bv1.x, bv1.x), pack2(bv1.y, bv1.y),
                                        pack2(bv1.z, bv1.z), pack2(bv1.w, bv1.w)};
#pragma unroll
            for (int i = 0; i < 4; ++i)
#pragma unroll
                for (int j = 0; j < 8; ++j) fma2(cc[i][j], av[i], bb[j]);
        }
        if (kt < NKT - 1) {
            const int nxt = cur ^ 1;
            As[nxt][aCol + 0][aRow] = a0.x; As[nxt][aCol + 1][aRow] = a0.y;
            As[nxt][aCol + 2][aRow] = a0.z; As[nxt][aCol + 3][aRow] = a0.w;
            As[nxt][aCol + 0][aRow + 64] = a1.x; As[nxt][aCol + 1][aRow + 64] = a1.y;
            As[nxt][aCol + 2][aRow + 64] = a1.z; As[nxt][aCol + 3][aRow + 64] = a1.w;
            *(float4*)&Bs[nxt][bRow][bCol]     = b0;
            *(float4*)&Bs[nxt][bRow + 8][bCol] = b1;
        }
        __syncthreads();
    }

    float bc[8];
#pragma unroll
    for (int j = 0; j < 8; ++j) bc[j] = bias[col0 + (j >> 2) * 64 + tx * 4 + (j & 3)];

#pragma unroll
    for (int i = 0; i < 4; ++i) {
        const int m = (i >> 1) * 64 + ty * 4 + (i & 1) * 2;
        float2 v[8];
#pragma unroll
        for (int j = 0; j < 8; ++j) v[j] = unpack2(cc[i][j]);
        size_t base = (size_t)(row0 + m) * D_SAE + col0;
        float4 o;
        o.x = v[0].x + bc[0]; o.y = v[1].x + bc[1]; o.z = v[2].x + bc[2]; o.w = v[3].x + bc[3];
        *(float4*)&g_pre[base + tx * 4] = o;
        o.x = v[4].x + bc[4]; o.y = v[5].x + bc[5]; o.z = v[6].x + bc[6]; o.w = v[7].x + bc[7];
        *(float4*)&g_pre[base + 64 + tx * 4] = o;
        base += D_SAE;
        o.x = v[0].y + bc[0]; o.y = v[1].y + bc[1]; o.z = v[2].y + bc[2]; o.w = v[3].y + bc[3];
        *(float4*)&g_pre[base + tx * 4] = o;
        o.x = v[4].y + bc[4]; o.y = v[5].y + bc[5]; o.z = v[6].y + bc[6]; o.w = v[7].y + bc[7];
        *(float4*)&g_pre[base + 64 + tx * 4] = o;
    }
}

// ======================================================================
// Kernel B: exact top-128 per row, emitted SORTED by composite desc.
// ======================================================================
#define TK_CAP 2816
__global__ __launch_bounds__(256, 2) void topk128() {
    __shared__ unsigned int hist[4096];
    __shared__ __align__(16) unsigned long long cand[TK_CAP];
    __shared__ unsigned int chunkSum[16];
    __shared__ int s_bin;
    __shared__ unsigned int s_cntHi, s_cntCand;
    __shared__ int sIdx[128];
    __shared__ float sVal[128];
    __shared__ __align__(16) unsigned long long sComp[128];

    const int row = blockIdx.x, tid = threadIdx.x;
    const float* rp = g_pre + (size_t)row * D_SAE;

    for (int i = tid; i < 4096; i += 256) hist[i] = 0;
    if (tid == 0) { s_cntHi = 0; s_cntCand = 0; }
    __syncthreads();

    float v[48];
#pragma unroll
    for (int i = 0; i < 12; ++i) {
        const float4 q = *(const float4*)(rp + (size_t)(tid + i * 256) * 4);
        v[i * 4 + 0] = q.x; v[i * 4 + 1] = q.y; v[i * 4 + 2] = q.z; v[i * 4 + 3] = q.w;
    }
#pragma unroll
    for (int i = 0; i < 48; ++i) atomicAdd(&hist[fkey(v[i]) >> 20], 1u);
    __syncthreads();

    if (tid < 16) {
        unsigned int s = 0;
        for (int j = 0; j < 256; ++j) s += hist[tid * 256 + j];
        chunkSum[tid] = s;
    }
    __syncthreads();
    if (tid == 0) {
        unsigned int cum = 0; int cb;
        for (cb = 15; cb > 0; --cb) {
            if (cum + chunkSum[cb] >= 128u) break;
            cum += chunkSum[cb];
        }
        int bin;
        for (bin = cb * 256 + 255; bin > cb * 256; --bin) {
            if (cum + hist[bin] >= 128u) break;
            cum += hist[bin];
        }
        s_bin = bin;
    }
    __syncthreads();

    const int tb = s_bin;
#pragma unroll
    for (int i = 0; i < 48; ++i) {
        const unsigned int k = fkey(v[i]);
        const int bin = (int)(k >> 20);
        if (bin >= tb) {
            const int idx = (tid + (i >> 2) * 256) * 4 + (i & 3);
            if (bin > tb) {
                unsigned int p = atomicAdd(&s_cntHi, 1u);
                sIdx[p] = idx; sVal[p] = v[i];
            } else {
                unsigned int q = atomicAdd(&s_cntCand, 1u);
                if (q < TK_CAP) cand[q] = makeComp(v[i], idx);
            }
        }
    }
    __syncthreads();

    const int need = 128 - (int)s_cntHi;
    const int nc = min((int)s_cntCand, TK_CAP);
    for (int c = tid; c < nc; c += 256) {
        const unsigned long long me = cand[c];
        int r = 0;
        for (int j = 0; j < nc; ++j) r += (cand[j] > me);
        if (r < need) {
            const int pos = (int)s_cntHi + r;
            sIdx[pos] = (int)(0xFFFFFFFFu - (unsigned int)me);
            sVal[pos] = keyToFloat((unsigned int)(me >> 32));
        }
    }
    __syncthreads();

    if (tid < 128) sComp[tid] = makeComp(sVal[tid], sIdx[tid]);
    __syncthreads();
    if (tid < 128) {
        const unsigned long long me = sComp[tid];
        int r = 0;
#pragma unroll
        for (int j = 0; j < 128; j += 8) {
            const ulonglong2 c0 = *(const ulonglong2*)&sComp[j];
            const ulonglong2 c1 = *(const ulonglong2*)&sComp[j + 2];
            const ulonglong2 c2 = *(const ulonglong2*)&sComp[j + 4];
            const ulonglong2 c3 = *(const ulonglong2*)&sComp[j + 6];
            r += (c0.x > me) + (c0.y > me) + (c1.x > me) + (c1.y > me)
               + (c2.x > me) + (c2.y > me) + (c3.x > me) + (c3.y > me);
        }
        g_topidx[row * 128 + r] = sIdx[tid];
        g_topval[row * 128 + r] = sVal[tid];
    }
}

// ======================================================================
// Kernel C: scan, fully software-pipelined (R11 structure, gate FIXED:
// sigmoid applied at load; candGate always holds post-sigmoid gate).
// ======================================================================
__global__ __launch_bounds__(128) void scan_kernel(const float* __restrict__ gate_raw,
                                                   float* __restrict__ z_last) {
    __shared__ unsigned int bitmap[D_SAE / 32];
    __shared__ __align__(16) unsigned long long cand[128];
    __shared__ float candGate[128];
    __shared__ float candNextPre[128];
    __shared__ int   tmpIdx[KTOP];
    __shared__ float tmpVal[KTOP];
    __shared__ float tmpGate[KTOP];
    __shared__ int   tmpSlot[KTOP];
    __shared__ int   warpCnt[4];

    const int b = blockIdx.x, tid = threadIdx.x, lane = tid & 31, w = tid >> 5;
    const int row0 = b * T_LEN;
    const int lastRow = row0 + T_LEN - 1;

    for (int i = tid; i < D_SAE; i += 128) z_last[(size_t)b * D_SAE + i] = 0.0f;
    for (int i = tid; i < D_SAE / 32; i += 128) bitmap[i] = 0;

    // winner registers (valid for tid<64 once t>=1)
    int   wIdx = 0;
    float wVal = 0.0f, wGate = 0.0f, wNextPre = 0.0f;

    // new-candidate pipeline registers for step 0 (gate = SIGMOID(raw))
    int   nIdx = g_topidx[(size_t)row0 * 128 + tid];
    float nVal = g_topval[(size_t)row0 * 128 + tid];
    float gNew = sigmoidf(gate_raw[nIdx]);
    __syncthreads();

    for (int t = 0; t < T_LEN; ++t) {
        const int row = row0 + t;
        const int nrow = (row + 1 <= lastRow) ? row + 1 : lastRow;

        // ---- phase A: issue all gathers for this step's candidate superset ----
        const float specNew  = g_pre[(size_t)nrow * D_SAE + nIdx];
        const float specPrev = g_pre[(size_t)nrow * D_SAE + wIdx];
        const int flag = !((bitmap[nIdx >> 5] >> (nIdx & 31)) & 1u);
        const unsigned bal = __ballot_sync(0xFFFFFFFFu, flag);
        if (lane == 0) warpCnt[w] = __popc(bal);
        __syncthreads();   // S1

        // ---- phase B: build candidate array (registers only) ----
        int off = __popc(bal & ((1u << lane) - 1));
#pragma unroll
        for (int q = 0; q < 4; ++q) off += (q < w) ? warpCnt[q] : 0;
        const int totalNew = warpCnt[0] + warpCnt[1] + warpCnt[2] + warpCnt[3];
        const int doScatter = flag && (off < KTOP);
        if (doScatter) {
            cand[64 + off] = makeComp(nVal, nIdx);
            candGate[64 + off] = gNew;
        }
        if (tid < 64) {
            if (t > 0) {
                cand[tid] = makeComp(wGate * wVal + wNextPre, wIdx);
                candGate[tid] = wGate;
            } else {
                cand[tid] = 0ull;
            }
        }
        if (tid >= 64) {
            const int s = tid - 64;
            if (s >= min(totalNew, KTOP)) cand[tid] = 0ull;
        }
        __syncthreads();   // S2

        // ---- phase C: rank + spec stores + t+1 prefetch + clear old bits ----
        const unsigned long long me = cand[tid];
        int r0 = 0, r1 = 0, r2 = 0, r3 = 0;
#pragma unroll
        for (int j = 0; j < 128; j += 16) {
            const ulonglong2 c0 = *(const ulonglong2*)&cand[j];
            const ulonglong2 c1 = *(const ulonglong2*)&cand[j + 2];
            const ulonglong2 c2 = *(const ulonglong2*)&cand[j + 4];
            const ulonglong2 c3 = *(const ulonglong2*)&cand[j + 6];
            const ulonglong2 c4 = *(const ulonglong2*)&cand[j + 8];
            const ulonglong2 c5 = *(const ulonglong2*)&cand[j + 10];
            const ulonglong2 c6 = *(const ulonglong2*)&cand[j + 12];
            const ulonglong2 c7 = *(const ulonglong2*)&cand[j + 14];
            r0 += (c0.x > me) + (c0.y > me) + (c1.x > me) + (c1.y > me);
            r1 += (c2.x > me) + (c2.y > me) + (c3.x > me) + (c3.y > me);
            r2 += (c4.x > me) + (c4.y > me) + (c5.x > me) + (c5.y > me);
            r3 += (c6.x > me) + (c6.y > me) + (c7.x > me) + (c7.y > me);
        }
        const int r = r0 + r1 + r2 + r3;
        if (me != 0ull && r < KTOP) {
            tmpIdx[r]  = (int)(0xFFFFFFFFu - (unsigned int)me);
            tmpVal[r]  = fmaxf(keyToFloat((unsigned int)(me >> 32)), 0.0f);
            tmpGate[r] = candGate[tid];
            tmpSlot[r] = tid;
        }
        if (tid < 64) candNextPre[tid] = specPrev;
        if (doScatter) candNextPre[64 + off] = specNew;
        if (t > 0 && tid < 64) atomicAnd(&bitmap[wIdx >> 5], ~(1u << (wIdx & 31)));
        int nIdx2 = 0; float nVal2 = 0.0f, gNew2 = 0.0f;
        if (t + 1 < T_LEN) {
            nIdx2 = g_topidx[(size_t)(row + 1) * 128 + tid];
            nVal2 = g_topval[(size_t)(row + 1) * 128 + tid];
            gNew2 = sigmoidf(gate_raw[nIdx2]);
        }
        __syncthreads();   // S3

        // ---- phase D: writeback (winners -> registers, bitmap, output) ----
        if (tid < KTOP) {
            wIdx  = tmpIdx[tid];
            wVal  = tmpVal[tid];
            wGate = tmpGate[tid];
            wNextPre = candNextPre[tmpSlot[tid]];
            atomicOr(&bitmap[wIdx >> 5], 1u << (wIdx & 31));
            g_zidx[row * KTOP + tid] = wIdx;
            g_zval[row * KTOP + tid] = wVal;
            if (t == T_LEN - 1) z_last[(size_t)b * D_SAE + wIdx] = wVal;
        }
        nIdx = nIdx2; nVal = nVal2; gNew = gNew2;
        __syncthreads();   // S4
    }
}

// ======================================================================
// Kernel D: sparse decode + per-row squared error. (xhat only 4B-aligned)
// ======================================================================
__global__ __launch_bounds__(192) void decode_kernel(const float* __restrict__ X,
                                                     const float* __restrict__ Wd,
                                                     const float* __restrict__ b_dec,
                                                     float* __restrict__ xhat) {
    __shared__ int sIdx[KTOP];
    __shared__ float sVal[KTOP];
    __shared__ float red[192];
    const int row = blockIdx.x, tid = threadIdx.x;
    if (tid < KTOP) {
        sIdx[tid] = g_zidx[row * KTOP + tid];
        sVal[tid] = g_zval[row * KTOP + tid];
    }
    __syncthreads();

    float4 acc = *(const float4*)(b_dec + tid * 4);
#pragma unroll 4
    for (int k = 0; k < KTOP; ++k) {
        const float v = sVal[k];
        const float4 wv = *(const float4*)(Wd + (size_t)sIdx[k] * D_IN + tid * 4);
        acc.x += v * wv.x; acc.y += v * wv.y; acc.z += v * wv.z; acc.w += v * wv.w;
    }
    float* op = xhat + (size_t)row * D_IN + tid * 4;
    op[0] = acc.x; op[1] = acc.y; op[2] = acc.z; op[3] = acc.w;

    const float4 xv = *(const float4*)(X + (size_t)row * D_IN + tid * 4);
    const float dx = acc.x - xv.x, dy = acc.y - xv.y, dz = acc.z - xv.z, dw = acc.w - xv.w;
    red[tid] = dx * dx + dy * dy + dz * dz + dw * dw;
    __syncthreads();
    for (int s = 96; s >= 6; s >>= 1) {
        if (tid < s) red[tid] += red[tid + s];
        __syncthreads();
    }
    if (tid == 0) {
        float total = 0.f;
        for (int i = 0; i < 6; ++i) total += red[i];
        g_rowloss[row] = total;
    }
}

// ======================================================================
// Finalization
// ======================================================================
__global__ __launch_bounds__(1024) void loss_kernel(float* __restrict__ out) {
    __shared__ float red[1024];
    const int tid = threadIdx.x;
    red[tid] = g_rowloss[tid] + g_rowloss[tid + 1024];
    __syncthreads();
    for (int s = 512; s > 0; s >>= 1) {
        if (tid < s) red[tid] += red[tid + s];
        __syncthreads();
    }
    if (tid == 0) out[0] = red[0] / (float)NROWS;
}

// ======================================================================
extern "C" void kernel_launch(void* const* d_in, const int* in_sizes, int n_in,
                              void* d_out, int out_size) {
    const float* x        = (const float*)d_in[0];
    const float* W_enc    = (const float*)d_in[1];
    const float* W_dec    = (const float*)d_in[2];
    const float* b_enc    = (const float*)d_in[3];
    const float* b_dec    = (const float*)d_in[4];
    const float* gate_raw = (const float*)d_in[5];

    float* out       = (float*)d_out;
    float* out_loss  = out;
    float* out_xhat  = out + 1;
    float* out_zlast = out + 1 + (size_t)NROWS * D_IN;

    dim3 gGrid(D_SAE / 128, NROWS / 128);  // (96, 16)
    gemm_enc<<<gGrid, 256>>>(x, W_enc, b_enc);
    topk128<<<NROWS, 256>>>();
    scan_kernel<<<BATCH, 128>>>(gate_raw, out_zlast);
    decode_kernel<<<NROWS, 192>>>(x, W_dec, b_dec, out_xhat);
    loss_kernel<<<1, 1024>>>(out_loss);
}

// round 13
// speedup vs baseline: 1.0663x; 1.0663x over previous
#include <cuda_runtime.h>
#include <cstdint>

#define D_IN   768
#define D_SAE  12288
#define T_LEN  64
#define KTOP   64
#define BATCH  32
#define NROWS  (BATCH * T_LEN)   // 2048

// ---------------- scratch (static device globals; no allocations) ----------------
__device__ __align__(16) float g_pre[(size_t)NROWS * D_SAE];     // 96 MB (exact fp32)
__device__ int   g_topidx[NROWS * 128];   // SORTED by composite desc
__device__ float g_topval[NROWS * 128];
__device__ int   g_zidx[NROWS * KTOP];
__device__ float g_zval[NROWS * KTOP];
__device__ float g_rowloss[NROWS];

// ---------------- helpers ----------------
__device__ __forceinline__ unsigned long long pack2(float x, float y) {
    unsigned long long r;
    asm("mov.b64 %0, {%1, %2};" : "=l"(r) : "f"(x), "f"(y));
    return r;
}
__device__ __forceinline__ float2 unpack2(unsigned long long v) {
    float2 f;
    asm("mov.b64 {%0, %1}, %2;" : "=f"(f.x), "=f"(f.y) : "l"(v));
    return f;
}
__device__ __forceinline__ void fma2(unsigned long long& c, unsigned long long a, unsigned long long b) {
    asm("fma.rn.f32x2 %0, %1, %2, %0;" : "+l"(c) : "l"(a), "l"(b));
}
__device__ __forceinline__ unsigned int fkey(float v) {
    unsigned int u = __float_as_uint(v);
    return (u & 0x80000000u) ? ~u : (u | 0x80000000u);
}
__device__ __forceinline__ float keyToFloat(unsigned int k) {
    unsigned int u = (k & 0x80000000u) ? (k & 0x7FFFFFFFu) : ~k;
    return __uint_as_float(u);
}
// larger == (greater value) or (equal value, smaller index)  [jax top_k tie rule]
__device__ __forceinline__ unsigned long long makeComp(float v, int idx) {
    return ((unsigned long long)fkey(v) << 32) | (unsigned long long)(0xFFFFFFFFu - (unsigned int)idx);
}

// ======================================================================
// Kernel A: fp32 GEMM (proven variant; at the FFMA2 rt=3 roofline).
// ======================================================================
__global__ __launch_bounds__(256, 1) void gemm_enc(const float* __restrict__ X,
                                                   const float* __restrict__ W,
                                                   const float* __restrict__ bias) {
    __shared__ __align__(16) float As[2][16][128];
    __shared__ __align__(16) float Bs[2][16][128];

    const int tid  = threadIdx.x;
    const int row0 = blockIdx.y * 128;
    const int col0 = blockIdx.x * 128;
    const int tx = tid & 15, ty = tid >> 4;

    const int aRow = tid >> 2;
    const int aCol = (tid & 3) * 4;
    const int bRow = tid >> 5;
    const int bCol = (tid & 31) * 4;

    const float* Aptr = X + (size_t)row0 * D_IN;
    const float* Bptr = W + col0;

    float4 a0, a1, b0, b1;
    a0 = *(const float4*)(Aptr + (size_t)aRow * D_IN + aCol);
    a1 = *(const float4*)(Aptr + (size_t)(aRow + 64) * D_IN + aCol);
    b0 = *(const float4*)(Bptr + (size_t)bRow * D_SAE + bCol);
    b1 = *(const float4*)(Bptr + (size_t)(bRow + 8) * D_SAE + bCol);
    As[0][aCol + 0][aRow] = a0.x; As[0][aCol + 1][aRow] = a0.y;
    As[0][aCol + 2][aRow] = a0.z; As[0][aCol + 3][aRow] = a0.w;
    As[0][aCol + 0][aRow + 64] = a1.x; As[0][aCol + 1][aRow + 64] = a1.y;
    As[0][aCol + 2][aRow + 64] = a1.z; As[0][aCol + 3][aRow + 64] = a1.w;
    *(float4*)&Bs[0][bRow][bCol]     = b0;
    *(float4*)&Bs[0][bRow + 8][bCol] = b1;
    __syncthreads();

    unsigned long long cc[4][8];
#pragma unroll
    for (int i = 0; i < 4; ++i)
#pragma unroll
        for (int j = 0; j < 8; ++j) cc[i][j] = 0ull;

    const int NKT = D_IN / 16;  // 48
    for (int kt = 0; kt < NKT; ++kt) {
        const int cur = kt & 1;
        if (kt < NKT - 1) {
            const int k0 = (kt + 1) * 16;
            a0 = *(const float4*)(Aptr + (size_t)aRow * D_IN + k0 + aCol);
            a1 = *(const float4*)(Aptr + (size_t)(aRow + 64) * D_IN + k0 + aCol);
            b0 = *(const float4*)(Bptr + (size_t)(k0 + bRow) * D_SAE + bCol);
            b1 = *(const float4*)(Bptr + (size_t)(k0 + bRow + 8) * D_SAE + bCol);
        }
#pragma unroll
        for (int k = 0; k < 16; ++k) {
            ulonglong2 aa01 = *(const ulonglong2*)&As[cur][k][ty * 4];
            ulonglong2 aa23 = *(const ulonglong2*)&As[cur][k][64 + ty * 4];
            float4 bv0 = *(const float4*)&Bs[cur][k][tx * 4];
            float4 bv1 = *(const float4*)&Bs[cur][k][64 + tx * 4];
            unsigned long long av[4] = {aa01.x, aa01.y, aa23.x, aa23.y};
            unsigned long long bb[8] = {pack2(bv0.x, bv0.x), pack2(bv0.y, bv0.y),
                                        pack2(bv0.z, bv0.z), pack2(bv0.w, bv0.w),
                                        pack2(bv1.x, bv1.x), pack2(bv1.y, bv1.y),
                                        pack2(bv1.z, bv1.z), pack2(bv1.w, bv1.w)};
#pragma unroll
            for (int i = 0; i < 4; ++i)
#pragma unroll
                for (int j = 0; j < 8; ++j) fma2(cc[i][j], av[i], bb[j]);
        }
        if (kt < NKT - 1) {
            const int nxt = cur ^ 1;
            As[nxt][aCol + 0][aRow] = a0.x; As[nxt][aCol + 1][aRow] = a0.y;
            As[nxt][aCol + 2][aRow] = a0.z; As[nxt][aCol + 3][aRow] = a0.w;
            As[nxt][aCol + 0][aRow + 64] = a1.x; As[nxt][aCol + 1][aRow + 64] = a1.y;
            As[nxt][aCol + 2][aRow + 64] = a1.z; As[nxt][aCol + 3][aRow + 64] = a1.w;
            *(float4*)&Bs[nxt][bRow][bCol]     = b0;
            *(float4*)&Bs[nxt][bRow + 8][bCol] = b1;
        }
        __syncthreads();
    }

    float bc[8];
#pragma unroll
    for (int j = 0; j < 8; ++j) bc[j] = bias[col0 + (j >> 2) * 64 + tx * 4 + (j & 3)];

#pragma unroll
    for (int i = 0; i < 4; ++i) {
        const int m = (i >> 1) * 64 + ty * 4 + (i & 1) * 2;
        float2 v[8];
#pragma unroll
        for (int j = 0; j < 8; ++j) v[j] = unpack2(cc[i][j]);
        size_t base = (size_t)(row0 + m) * D_SAE + col0;
        float4 o;
        o.x = v[0].x + bc[0]; o.y = v[1].x + bc[1]; o.z = v[2].x + bc[2]; o.w = v[3].x + bc[3];
        *(float4*)&g_pre[base + tx * 4] = o;
        o.x = v[4].x + bc[4]; o.y = v[5].x + bc[5]; o.z = v[6].x + bc[6]; o.w = v[7].x + bc[7];
        *(float4*)&g_pre[base + 64 + tx * 4] = o;
        base += D_SAE;
        o.x = v[0].y + bc[0]; o.y = v[1].y + bc[1]; o.z = v[2].y + bc[2]; o.w = v[3].y + bc[3];
        *(float4*)&g_pre[base + tx * 4] = o;
        o.x = v[4].y + bc[4]; o.y = v[5].y + bc[5]; o.z = v[6].y + bc[6]; o.w = v[7].y + bc[7];
        *(float4*)&g_pre[base + 64 + tx * 4] = o;
    }
}

// ======================================================================
// Kernel B: exact top-128 per row via threshold-from-maxes (no histogram).
// T = 128th-largest of 256 per-thread maxes  =>  top-128 subset of {v>=T}.
// Collect candidates >= T (warp-aggregated), exact rank -> sorted output.
// ======================================================================
#define TK_CAP 4096
__global__ __launch_bounds__(256, 2) void topk128() {
    __shared__ __align__(16) float sMax[256];
    __shared__ __align__(16) unsigned long long cand[TK_CAP + 8];
    __shared__ unsigned int sTkey;
    __shared__ int sCount;

    const int row = blockIdx.x, tid = threadIdx.x, lane = tid & 31;
    const float* rp = g_pre + (size_t)row * D_SAE;

    // single DRAM pass: row held in registers
    float v[48];
#pragma unroll
    for (int i = 0; i < 12; ++i) {
        const float4 q = *(const float4*)(rp + (size_t)(tid + i * 256) * 4);
        v[i * 4 + 0] = q.x; v[i * 4 + 1] = q.y; v[i * 4 + 2] = q.z; v[i * 4 + 3] = q.w;
    }
    float m = v[0];
#pragma unroll
    for (int i = 1; i < 48; ++i) m = fmaxf(m, v[i]);
    sMax[tid] = m;
    if (tid == 0) { sTkey = 0xFFFFFFFFu; sCount = 0; }
    __syncthreads();

    // rank my max among 256 maxes (strict-greater); qualifiers set T via atomicMin
    {
        const unsigned int mk = fkey(m);
        int r = 0;
#pragma unroll
        for (int j = 0; j < 256; j += 4) {
            const float4 q = *(const float4*)&sMax[j];
            r += (fkey(q.x) > mk) + (fkey(q.y) > mk) + (fkey(q.z) > mk) + (fkey(q.w) > mk);
        }
        if (r <= 127) atomicMin(&sTkey, mk);
    }
    __syncthreads();
    const unsigned int T = sTkey;

    // collect candidates with fkey >= T (warp-aggregated append)
#pragma unroll
    for (int i = 0; i < 48; ++i) {
        const int flag = (fkey(v[i]) >= T);
        const unsigned bal = __ballot_sync(0xFFFFFFFFu, flag);
        if (bal) {
            int base = 0;
            if (lane == 0) base = atomicAdd(&sCount, __popc(bal));
            base = __shfl_sync(0xFFFFFFFFu, base, 0);
            if (flag) {
                const int pos = base + __popc(bal & ((1u << lane) - 1));
                if (pos < TK_CAP) {
                    const int idx = (tid + (i >> 2) * 256) * 4 + (i & 3);
                    cand[pos] = makeComp(v[i], idx);
                }
            }
        }
    }
    __syncthreads();

    const int nc = min(sCount, TK_CAP);
    // pad for unrolled reads
    if (tid < 8) cand[nc + tid] = 0ull;
    __syncthreads();

    // exact rank among candidates -> sorted top-128 written directly
    for (int c = tid; c < nc; c += 256) {
        const unsigned long long me = cand[c];
        int r = 0;
        for (int j = 0; j < nc; j += 8) {
            const ulonglong2 c0 = *(const ulonglong2*)&cand[j];
            const ulonglong2 c1 = *(const ulonglong2*)&cand[j + 2];
            const ulonglong2 c2 = *(const ulonglong2*)&cand[j + 4];
            const ulonglong2 c3 = *(const ulonglong2*)&cand[j + 6];
            r += (c0.x > me) + (c0.y > me) + (c1.x > me) + (c1.y > me)
               + (c2.x > me) + (c2.y > me) + (c3.x > me) + (c3.y > me);
        }
        if (r < 128) {
            g_topidx[row * 128 + r] = (int)(0xFFFFFFFFu - (unsigned int)me);
            g_topval[row * 128 + r] = keyToFloat((unsigned int)(me >> 32));
        }
    }
}

// ======================================================================
// Kernel C: sequential scan (R9 measured-best version, verbatim math).
// ======================================================================
__global__ __launch_bounds__(128) void scan_kernel(const float* __restrict__ gate_raw,
                                                   float* __restrict__ z_last) {
    __shared__ unsigned int bitmap[D_SAE / 32];
    __shared__ int prevIdx[KTOP];
    __shared__ float prevVal[KTOP];
    __shared__ __align__(16) unsigned long long cand[128];
    __shared__ int tmpIdx[KTOP];
    __shared__ float tmpVal[KTOP];
    __shared__ int warpCnt[4];

    const int b = blockIdx.x, tid = threadIdx.x, lane = tid & 31, w = tid >> 5;

    for (int i = tid; i < D_SAE; i += 128) z_last[(size_t)b * D_SAE + i] = 0.0f;
    for (int i = tid; i < D_SAE / 32; i += 128) bitmap[i] = 0;
    int nprev = 0;

    int nIdx = g_topidx[(size_t)(b * T_LEN) * 128 + tid];
    float nVal = g_topval[(size_t)(b * T_LEN) * 128 + tid];
    __syncthreads();

    for (int t = 0; t < T_LEN; ++t) {
        const int row = b * T_LEN + t;

        if (tid < nprev) {
            const int idx = prevIdx[tid];
            const float pre = g_pre[(size_t)row * D_SAE + idx];
            const float gate_e = 1.0f / (1.0f + expf(-gate_raw[idx]));
            cand[tid] = makeComp(gate_e * prevVal[tid] + pre, idx);
        } else if (tid < 64) {
            cand[tid] = 0ull;
        }
        const int flag = !((bitmap[nIdx >> 5] >> (nIdx & 31)) & 1u);
        const unsigned bal = __ballot_sync(0xFFFFFFFFu, flag);
        if (lane == 0) warpCnt[w] = __popc(bal);
        __syncthreads();

        int off = __popc(bal & ((1u << lane) - 1));
#pragma unroll
        for (int q = 0; q < 4; ++q) off += (q < w) ? warpCnt[q] : 0;
        const int totalNew = warpCnt[0] + warpCnt[1] + warpCnt[2] + warpCnt[3];
        if (flag && off < KTOP) cand[64 + off] = makeComp(nVal, nIdx);
        {
            const int s = tid;
            if (s >= min(totalNew, KTOP)) cand[64 + s] = (s < 64) ? cand[64 + s] : 0ull;
        }
        // sentinel-reset of unused new slots
        if (tid < 64 - min(totalNew, KTOP)) cand[64 + min(totalNew, KTOP) + tid] = 0ull;
        __syncthreads();

        if (tid < nprev) atomicAnd(&bitmap[prevIdx[tid] >> 5], ~(1u << (prevIdx[tid] & 31)));
        int nIdx2 = 0; float nVal2 = 0.0f;
        if (t + 1 < T_LEN) {
            nIdx2 = g_topidx[(size_t)(row + 1) * 128 + tid];
            nVal2 = g_topval[(size_t)(row + 1) * 128 + tid];
        }

        {
            const unsigned long long me = cand[tid];
            int r = 0;
#pragma unroll
            for (int j = 0; j < 128; j += 8) {
                const ulonglong2 c0 = *(const ulonglong2*)&cand[j];
                const ulonglong2 c1 = *(const ulonglong2*)&cand[j + 2];
                const ulonglong2 c2 = *(const ulonglong2*)&cand[j + 4];
                const ulonglong2 c3 = *(const ulonglong2*)&cand[j + 6];
                r += (c0.x > me) + (c0.y > me) + (c1.x > me) + (c1.y > me)
                   + (c2.x > me) + (c2.y > me) + (c3.x > me) + (c3.y > me);
            }
            if (me != 0ull && r < KTOP) {
                tmpIdx[r] = (int)(0xFFFFFFFFu - (unsigned int)me);
                tmpVal[r] = fmaxf(keyToFloat((unsigned int)(me >> 32)), 0.0f);
            }
        }
        __syncthreads();

        if (tid < KTOP) {
            const int idx = tmpIdx[tid];
            const float vv = tmpVal[tid];
            prevIdx[tid] = idx; prevVal[tid] = vv;
            atomicOr(&bitmap[idx >> 5], 1u << (idx & 31));
            g_zidx[row * KTOP + tid] = idx;
            g_zval[row * KTOP + tid] = vv;
            if (t == T_LEN - 1) z_last[(size_t)b * D_SAE + idx] = vv;
        }
        nprev = KTOP;
        nIdx = nIdx2; nVal = nVal2;
        __syncthreads();
    }
}

// ======================================================================
// Kernel D: sparse decode + per-row squared error. (xhat only 4B-aligned)
// ======================================================================
__global__ __launch_bounds__(192) void decode_kernel(const float* __restrict__ X,
                                                     const float* __restrict__ Wd,
                                                     const float* __restrict__ b_dec,
                                                     float* __restrict__ xhat) {
    __shared__ int sIdx[KTOP];
    __shared__ float sVal[KTOP];
    __shared__ float red[192];
    const int row = blockIdx.x, tid = threadIdx.x;
    if (tid < KTOP) {
        sIdx[tid] = g_zidx[row * KTOP + tid];
        sVal[tid] = g_zval[row * KTOP + tid];
    }
    __syncthreads();

    float4 acc = *(const float4*)(b_dec + tid * 4);
#pragma unroll 4
    for (int k = 0; k < KTOP; ++k) {
        const float v = sVal[k];
        const float4 wv = *(const float4*)(Wd + (size_t)sIdx[k] * D_IN + tid * 4);
        acc.x += v * wv.x; acc.y += v * wv.y; acc.z += v * wv.z; acc.w += v * wv.w;
    }
    float* op = xhat + (size_t)row * D_IN + tid * 4;
    op[0] = acc.x; op[1] = acc.y; op[2] = acc.z; op[3] = acc.w;

    const float4 xv = *(const float4*)(X + (size_t)row * D_IN + tid * 4);
    const float dx = acc.x - xv.x, dy = acc.y - xv.y, dz = acc.z - xv.z, dw = acc.w - xv.w;
    red[tid] = dx * dx + dy * dy + dz * dz + dw * dw;
    __syncthreads();
    for (int s = 96; s >= 6; s >>= 1) {
        if (tid < s) red[tid] += red[tid + s];
        __syncthreads();
    }
    if (tid == 0) {
        float total = 0.f;
        for (int i = 0; i < 6; ++i) total += red[i];
        g_rowloss[row] = total;
    }
}

// ======================================================================
// Finalization
// ======================================================================
__global__ __launch_bounds__(1024) void loss_kernel(float* __restrict__ out) {
    __shared__ float red[1024];
    const int tid = threadIdx.x;
    red[tid] = g_rowloss[tid] + g_rowloss[tid + 1024];
    __syncthreads();
    for (int s = 512; s > 0; s >>= 1) {
        if (tid < s) red[tid] += red[tid + s];
        __syncthreads();
    }
    if (tid == 0) out[0] = red[0] / (float)NROWS;
}

// ======================================================================
extern "C" void kernel_launch(void* const* d_in, const int* in_sizes, int n_in,
                              void* d_out, int out_size) {
    const float* x        = (const float*)d_in[0];
    const float* W_enc    = (const float*)d_in[1];
    const float* W_dec    = (const float*)d_in[2];
    const float* b_enc    = (const float*)d_in[3];
    const float* b_dec    = (const float*)d_in[4];
    const float* gate_raw = (const float*)d_in[5];

    float* out       = (float*)d_out;
    float* out_loss  = out;
    float* out_xhat  = out + 1;
    float* out_zlast = out + 1 + (size_t)NROWS * D_IN;

    dim3 gGrid(D_SAE / 128, NROWS / 128);  // (96, 16)
    gemm_enc<<<gGrid, 256>>>(x, W_enc, b_enc);
    topk128<<<NROWS, 256>>>();
    scan_kernel<<<BATCH, 128>>>(gate_raw, out_zlast);
    decode_kernel<<<NROWS, 192>>>(x, W_dec, b_dec, out_xhat);
    loss_kernel<<<1, 1024>>>(out_loss);
}

// round 14
// speedup vs baseline: 1.0783x; 1.0113x over previous
#include <cuda_runtime.h>
#include <cstdint>

#define D_IN   768
#define D_SAE  12288
#define T_LEN  64
#define KTOP   64
#define BATCH  32
#define NROWS  (BATCH * T_LEN)   // 2048

// ---------------- scratch (static device globals; no allocations) ----------------
__device__ __align__(16) float g_pre[(size_t)NROWS * D_SAE];     // 96 MB (exact fp32)
__device__ float g_gate[D_SAE];
__device__ int   g_topidx[NROWS * 128];   // SORTED by composite desc
__device__ float g_topval[NROWS * 128];
__device__ int   g_zidx[NROWS * KTOP];
__device__ float g_zval[NROWS * KTOP];
__device__ float g_rowloss[NROWS];

// ---------------- helpers ----------------
__device__ __forceinline__ unsigned long long pack2(float x, float y) {
    unsigned long long r;
    asm("mov.b64 %0, {%1, %2};" : "=l"(r) : "f"(x), "f"(y));
    return r;
}
__device__ __forceinline__ float2 unpack2(unsigned long long v) {
    float2 f;
    asm("mov.b64 {%0, %1}, %2;" : "=f"(f.x), "=f"(f.y) : "l"(v));
    return f;
}
__device__ __forceinline__ void fma2(unsigned long long& c, unsigned long long a, unsigned long long b) {
    asm("fma.rn.f32x2 %0, %1, %2, %0;" : "+l"(c) : "l"(a), "l"(b));
}
__device__ __forceinline__ unsigned int fkey(float v) {
    unsigned int u = __float_as_uint(v);
    return (u & 0x80000000u) ? ~u : (u | 0x80000000u);
}
__device__ __forceinline__ float keyToFloat(unsigned int k) {
    unsigned int u = (k & 0x80000000u) ? (k & 0x7FFFFFFFu) : ~k;
    return __uint_as_float(u);
}
// larger == (greater value) or (equal value, smaller index)  [jax top_k tie rule]
__device__ __forceinline__ unsigned long long makeComp(float v, int idx) {
    return ((unsigned long long)fkey(v) << 32) | (unsigned long long)(0xFFFFFFFFu - (unsigned int)idx);
}

// ======================================================================
// Kernel A: fp32 GEMM (proven variant; at the FFMA2 rt=3 roofline).
// ======================================================================
__global__ __launch_bounds__(256, 1) void gemm_enc(const float* __restrict__ X,
                                                   const float* __restrict__ W,
                                                   const float* __restrict__ bias) {
    __shared__ __align__(16) float As[2][16][128];
    __shared__ __align__(16) float Bs[2][16][128];

    const int tid  = threadIdx.x;
    const int row0 = blockIdx.y * 128;
    const int col0 = blockIdx.x * 128;
    const int tx = tid & 15, ty = tid >> 4;

    const int aRow = tid >> 2;
    const int aCol = (tid & 3) * 4;
    const int bRow = tid >> 5;
    const int bCol = (tid & 31) * 4;

    const float* Aptr = X + (size_t)row0 * D_IN;
    const float* Bptr = W + col0;

    float4 a0, a1, b0, b1;
    a0 = *(const float4*)(Aptr + (size_t)aRow * D_IN + aCol);
    a1 = *(const float4*)(Aptr + (size_t)(aRow + 64) * D_IN + aCol);
    b0 = *(const float4*)(Bptr + (size_t)bRow * D_SAE + bCol);
    b1 = *(const float4*)(Bptr + (size_t)(bRow + 8) * D_SAE + bCol);
    As[0][aCol + 0][aRow] = a0.x; As[0][aCol + 1][aRow] = a0.y;
    As[0][aCol + 2][aRow] = a0.z; As[0][aCol + 3][aRow] = a0.w;
    As[0][aCol + 0][aRow + 64] = a1.x; As[0][aCol + 1][aRow + 64] = a1.y;
    As[0][aCol + 2][aRow + 64] = a1.z; As[0][aCol + 3][aRow + 64] = a1.w;
    *(float4*)&Bs[0][bRow][bCol]     = b0;
    *(float4*)&Bs[0][bRow + 8][bCol] = b1;
    __syncthreads();

    unsigned long long cc[4][8];
#pragma unroll
    for (int i = 0; i < 4; ++i)
#pragma unroll
        for (int j = 0; j < 8; ++j) cc[i][j] = 0ull;

    const int NKT = D_IN / 16;  // 48
    for (int kt = 0; kt < NKT; ++kt) {
        const int cur = kt & 1;
        if (kt < NKT - 1) {
            const int k0 = (kt + 1) * 16;
            a0 = *(const float4*)(Aptr + (size_t)aRow * D_IN + k0 + aCol);
            a1 = *(const float4*)(Aptr + (size_t)(aRow + 64) * D_IN + k0 + aCol);
            b0 = *(const float4*)(Bptr + (size_t)(k0 + bRow) * D_SAE + bCol);
            b1 = *(const float4*)(Bptr + (size_t)(k0 + bRow + 8) * D_SAE + bCol);
        }
#pragma unroll
        for (int k = 0; k < 16; ++k) {
            ulonglong2 aa01 = *(const ulonglong2*)&As[cur][k][ty * 4];
            ulonglong2 aa23 = *(const ulonglong2*)&As[cur][k][64 + ty * 4];
            float4 bv0 = *(const float4*)&Bs[cur][k][tx * 4];
            float4 bv1 = *(const float4*)&Bs[cur][k][64 + tx * 4];
            unsigned long long av[4] = {aa01.x, aa01.y, aa23.x, aa23.y};
            unsigned long long bb[8] = {pack2(bv0.x, bv0.x), pack2(bv0.y, bv0.y),
                                        pack2(bv0.z, bv0.z), pack2(bv0.w, bv0.w),
                                        pack2(bv1.x, bv1.x), pack2(bv1.y, bv1.y),
                                        pack2(bv1.z, bv1.z), pack2(bv1.w, bv1.w)};
#pragma unroll
            for (int i = 0; i < 4; ++i)
#pragma unroll
                for (int j = 0; j < 8; ++j) fma2(cc[i][j], av[i], bb[j]);
        }
        if (kt < NKT - 1) {
            const int nxt = cur ^ 1;
            As[nxt][aCol + 0][aRow] = a0.x; As[nxt][aCol + 1][aRow] = a0.y;
            As[nxt][aCol + 2][aRow] = a0.z; As[nxt][aCol + 3][aRow] = a0.w;
            As[nxt][aCol + 0][aRow + 64] = a1.x; As[nxt][aCol + 1][aRow + 64] = a1.y;
            As[nxt][aCol + 2][aRow + 64] = a1.z; As[nxt][aCol + 3][aRow + 64] = a1.w;
            *(float4*)&Bs[nxt][bRow][bCol]     = b0;
            *(float4*)&Bs[nxt][bRow + 8][bCol] = b1;
        }
        __syncthreads();
    }

    float bc[8];
#pragma unroll
    for (int j = 0; j < 8; ++j) bc[j] = bias[col0 + (j >> 2) * 64 + tx * 4 + (j & 3)];

#pragma unroll
    for (int i = 0; i < 4; ++i) {
        const int m = (i >> 1) * 64 + ty * 4 + (i & 1) * 2;
        float2 v[8];
#pragma unroll
        for (int j = 0; j < 8; ++j) v[j] = unpack2(cc[i][j]);
        size_t base = (size_t)(row0 + m) * D_SAE + col0;
        float4 o;
        o.x = v[0].x + bc[0]; o.y = v[1].x + bc[1]; o.z = v[2].x + bc[2]; o.w = v[3].x + bc[3];
        *(float4*)&g_pre[base + tx * 4] = o;
        o.x = v[4].x + bc[4]; o.y = v[5].x + bc[5]; o.z = v[6].x + bc[6]; o.w = v[7].x + bc[7];
        *(float4*)&g_pre[base + 64 + tx * 4] = o;
        base += D_SAE;
        o.x = v[0].y + bc[0]; o.y = v[1].y + bc[1]; o.z = v[2].y + bc[2]; o.w = v[3].y + bc[3];
        *(float4*)&g_pre[base + tx * 4] = o;
        o.x = v[4].y + bc[4]; o.y = v[5].y + bc[5]; o.z = v[6].y + bc[6]; o.w = v[7].y + bc[7];
        *(float4*)&g_pre[base + 64 + tx * 4] = o;
    }
}

// ======================================================================
// gate table: g_gate[i] = sigmoid(gate_raw[i])  (bit-identical formula)
// ======================================================================
__global__ __launch_bounds__(256) void gate_kernel(const float* __restrict__ gate_raw) {
    const int i = blockIdx.x * 256 + threadIdx.x;
    if (i < D_SAE) g_gate[i] = 1.0f / (1.0f + expf(-gate_raw[i]));
}

// ======================================================================
// Kernel B: exact top-128 per row via threshold-from-maxes (no histogram).
// ======================================================================
#define TK_CAP 4096
__global__ __launch_bounds__(256, 2) void topk128() {
    __shared__ __align__(16) float sMax[256];
    __shared__ __align__(16) unsigned long long cand[TK_CAP + 8];
    __shared__ unsigned int sTkey;
    __shared__ int sCount;

    const int row = blockIdx.x, tid = threadIdx.x, lane = tid & 31;
    const float* rp = g_pre + (size_t)row * D_SAE;

    float v[48];
#pragma unroll
    for (int i = 0; i < 12; ++i) {
        const float4 q = *(const float4*)(rp + (size_t)(tid + i * 256) * 4);
        v[i * 4 + 0] = q.x; v[i * 4 + 1] = q.y; v[i * 4 + 2] = q.z; v[i * 4 + 3] = q.w;
    }
    float m = v[0];
#pragma unroll
    for (int i = 1; i < 48; ++i) m = fmaxf(m, v[i]);
    sMax[tid] = m;
    if (tid == 0) { sTkey = 0xFFFFFFFFu; sCount = 0; }
    __syncthreads();

    {
        const unsigned int mk = fkey(m);
        int r = 0;
#pragma unroll
        for (int j = 0; j < 256; j += 4) {
            const float4 q = *(const float4*)&sMax[j];
            r += (fkey(q.x) > mk) + (fkey(q.y) > mk) + (fkey(q.z) > mk) + (fkey(q.w) > mk);
        }
        if (r <= 127) atomicMin(&sTkey, mk);
    }
    __syncthreads();
    const unsigned int T = sTkey;

#pragma unroll
    for (int i = 0; i < 48; ++i) {
        const int flag = (fkey(v[i]) >= T);
        const unsigned bal = __ballot_sync(0xFFFFFFFFu, flag);
        if (bal) {
            int base = 0;
            if (lane == 0) base = atomicAdd(&sCount, __popc(bal));
            base = __shfl_sync(0xFFFFFFFFu, base, 0);
            if (flag) {
                const int pos = base + __popc(bal & ((1u << lane) - 1));
                if (pos < TK_CAP) {
                    const int idx = (tid + (i >> 2) * 256) * 4 + (i & 3);
                    cand[pos] = makeComp(v[i], idx);
                }
            }
        }
    }
    __syncthreads();

    const int nc = min(sCount, TK_CAP);
    if (tid < 8) cand[nc + tid] = 0ull;
    __syncthreads();

    for (int c = tid; c < nc; c += 256) {
        const unsigned long long me = cand[c];
        int r = 0;
        for (int j = 0; j < nc; j += 8) {
            const ulonglong2 c0 = *(const ulonglong2*)&cand[j];
            const ulonglong2 c1 = *(const ulonglong2*)&cand[j + 2];
            const ulonglong2 c2 = *(const ulonglong2*)&cand[j + 4];
            const ulonglong2 c3 = *(const ulonglong2*)&cand[j + 6];
            r += (c0.x > me) + (c0.y > me) + (c1.x > me) + (c1.y > me)
               + (c2.x > me) + (c2.y > me) + (c3.x > me) + (c3.y > me);
        }
        if (r < 128) {
            g_topidx[row * 128 + r] = (int)(0xFFFFFFFFu - (unsigned int)me);
            g_topval[row * 128 + r] = keyToFloat((unsigned int)(me >> 32));
        }
    }
}

// ======================================================================
// Kernel C: scan (R9 control flow; gate table, register-resident winners,
// all independent loads hoisted to step start, composites built post-ballot).
// ======================================================================
__global__ __launch_bounds__(128) void scan_kernel(float* __restrict__ z_last) {
    __shared__ unsigned int bitmap[D_SAE / 32];
    __shared__ __align__(16) unsigned long long cand[128];
    __shared__ int tmpIdx[KTOP];
    __shared__ float tmpVal[KTOP];
    __shared__ int warpCnt[4];

    const int b = blockIdx.x, tid = threadIdx.x, lane = tid & 31, w = tid >> 5;
    const int row0 = b * T_LEN;

    for (int i = tid; i < D_SAE; i += 128) z_last[(size_t)b * D_SAE + i] = 0.0f;
    for (int i = tid; i < D_SAE / 32; i += 128) bitmap[i] = 0;

    // winner state in registers (thread tid owns winner slot tid, tid<64)
    int   pIdx = 0;
    float pVal = 0.0f;
    int nprev = 0;

    int   nIdx = g_topidx[(size_t)row0 * 128 + tid];
    float nVal = g_topval[(size_t)row0 * 128 + tid];
    __syncthreads();

    for (int t = 0; t < T_LEN; ++t) {
        const int row = row0 + t;

        // --- top of step: issue ALL independent loads ---
        float preV = 0.0f, gV = 0.0f;
        if (tid < nprev) {
            preV = g_pre[(size_t)row * D_SAE + pIdx];
            gV   = g_gate[pIdx];
        }
        int nIdx2 = 0; float nVal2 = 0.0f;
        if (t + 1 < T_LEN) {
            nIdx2 = g_topidx[(size_t)(row + 1) * 128 + tid];
            nVal2 = g_topval[(size_t)(row + 1) * 128 + tid];
        }

        // --- ballot/dedup (covers part of the gather latency) ---
        const int flag = !((bitmap[nIdx >> 5] >> (nIdx & 31)) & 1u);
        const unsigned bal = __ballot_sync(0xFFFFFFFFu, flag);
        if (lane == 0) warpCnt[w] = __popc(bal);
        __syncthreads();   // S1

        int off = __popc(bal & ((1u << lane) - 1));
#pragma unroll
        for (int q = 0; q < 4; ++q) off += (q < w) ? warpCnt[q] : 0;
        const int tn = min(warpCnt[0] + warpCnt[1] + warpCnt[2] + warpCnt[3], KTOP);
        if (flag && off < KTOP) cand[64 + off] = makeComp(nVal, nIdx);
        if (tid >= tn && tid < 64) cand[64 + tid] = 0ull;   // sentinel unused new slots
        if (tid < 64)
            cand[tid] = (tid < nprev) ? makeComp(gV * pVal + preV, pIdx) : 0ull;
        // clear old winners' bits (flags already consumed before S1)
        if (tid < nprev) atomicAnd(&bitmap[pIdx >> 5], ~(1u << (pIdx & 31)));
        __syncthreads();   // S2

        // --- exact rank over 128 candidates ---
        {
            const unsigned long long me = cand[tid];
            int r0 = 0, r1 = 0;
#pragma unroll
            for (int j = 0; j < 128; j += 16) {
                const ulonglong2 c0 = *(const ulonglong2*)&cand[j];
                const ulonglong2 c1 = *(const ulonglong2*)&cand[j + 2];
                const ulonglong2 c2 = *(const ulonglong2*)&cand[j + 4];
                const ulonglong2 c3 = *(const ulonglong2*)&cand[j + 6];
                const ulonglong2 c4 = *(const ulonglong2*)&cand[j + 8];
                const ulonglong2 c5 = *(const ulonglong2*)&cand[j + 10];
                const ulonglong2 c6 = *(const ulonglong2*)&cand[j + 12];
                const ulonglong2 c7 = *(const ulonglong2*)&cand[j + 14];
                r0 += (c0.x > me) + (c0.y > me) + (c1.x > me) + (c1.y > me)
                    + (c2.x > me) + (c2.y > me) + (c3.x > me) + (c3.y > me);
                r1 += (c4.x > me) + (c4.y > me) + (c5.x > me) + (c5.y > me)
                    + (c6.x > me) + (c6.y > me) + (c7.x > me) + (c7.y > me);
            }
            const int r = r0 + r1;
            if (me != 0ull && r < KTOP) {
                tmpIdx[r] = (int)(0xFFFFFFFFu - (unsigned int)me);
                tmpVal[r] = fmaxf(keyToFloat((unsigned int)(me >> 32)), 0.0f);
            }
        }
        __syncthreads();   // S3

        // --- writeback: winners into registers + bitmap + output ---
        if (tid < KTOP) {
            pIdx = tmpIdx[tid];
            pVal = tmpVal[tid];
            atomicOr(&bitmap[pIdx >> 5], 1u << (pIdx & 31));
            g_zidx[row * KTOP + tid] = pIdx;
            g_zval[row * KTOP + tid] = pVal;
            if (t == T_LEN - 1) z_last[(size_t)b * D_SAE + pIdx] = pVal;
        }
        nprev = KTOP;
        nIdx = nIdx2; nVal = nVal2;
        __syncthreads();   // S4
    }
}

// ======================================================================
// Kernel D: sparse decode + per-row squared error. (xhat only 4B-aligned)
// ======================================================================
__global__ __launch_bounds__(192) void decode_kernel(const float* __restrict__ X,
                                                     const float* __restrict__ Wd,
                                                     const float* __restrict__ b_dec,
                                                     float* __restrict__ xhat) {
    __shared__ int sIdx[KTOP];
    __shared__ float sVal[KTOP];
    __shared__ float red[192];
    const int row = blockIdx.x, tid = threadIdx.x;
    if (tid < KTOP) {
        sIdx[tid] = g_zidx[row * KTOP + tid];
        sVal[tid] = g_zval[row * KTOP + tid];
    }
    __syncthreads();

    float4 acc = *(const float4*)(b_dec + tid * 4);
#pragma unroll 4
    for (int k = 0; k < KTOP; ++k) {
        const float v = sVal[k];
        const float4 wv = *(const float4*)(Wd + (size_t)sIdx[k] * D_IN + tid * 4);
        acc.x += v * wv.x; acc.y += v * wv.y; acc.z += v * wv.z; acc.w += v * wv.w;
    }
    float* op = xhat + (size_t)row * D_IN + tid * 4;
    op[0] = acc.x; op[1] = acc.y; op[2] = acc.z; op[3] = acc.w;

    const float4 xv = *(const float4*)(X + (size_t)row * D_IN + tid * 4);
    const float dx = acc.x - xv.x, dy = acc.y - xv.y, dz = acc.z - xv.z, dw = acc.w - xv.w;
    red[tid] = dx * dx + dy * dy + dz * dz + dw * dw;
    __syncthreads();
    for (int s = 96; s >= 6; s >>= 1) {
        if (tid < s) red[tid] += red[tid + s];
        __syncthreads();
    }
    if (tid == 0) {
        float total = 0.f;
        for (int i = 0; i < 6; ++i) total += red[i];
        g_rowloss[row] = total;
    }
}

// ======================================================================
// Finalization
// ======================================================================
__global__ __launch_bounds__(1024) void loss_kernel(float* __restrict__ out) {
    __shared__ float red[1024];
    const int tid = threadIdx.x;
    red[tid] = g_rowloss[tid] + g_rowloss[tid + 1024];
    __syncthreads();
    for (int s = 512; s > 0; s >>= 1) {
        if (tid < s) red[tid] += red[tid + s];
        __syncthreads();
    }
    if (tid == 0) out[0] = red[0] / (float)NROWS;
}

// ======================================================================
extern "C" void kernel_launch(void* const* d_in, const int* in_sizes, int n_in,
                              void* d_out, int out_size) {
    const float* x        = (const float*)d_in[0];
    const float* W_enc    = (const float*)d_in[1];
    const float* W_dec    = (const float*)d_in[2];
    const float* b_enc    = (const float*)d_in[3];
    const float* b_dec    = (const float*)d_in[4];
    const float* gate_raw = (const float*)d_in[5];

    float* out       = (float*)d_out;
    float* out_loss  = out;
    float* out_xhat  = out + 1;
    float* out_zlast = out + 1 + (size_t)NROWS * D_IN;

    // order: gate(1) gemm(2) topk(3) scan(4 <- profiled) decode(5) loss(6)
    gate_kernel<<<(D_SAE + 255) / 256, 256>>>(gate_raw);
    dim3 gGrid(D_SAE / 128, NROWS / 128);  // (96, 16)
    gemm_enc<<<gGrid, 256>>>(x, W_enc, b_enc);
    topk128<<<NROWS, 256>>>();
    scan_kernel<<<BATCH, 128>>>(out_zlast);
    decode_kernel<<<NROWS, 192>>>(x, W_dec, b_dec, out_xhat);
    loss_kernel<<<1, 1024>>>(out_loss);
}

// round 15
// speedup vs baseline: 1.0789x; 1.0005x over previous
#include <cuda_runtime.h>
#include <cstdint>

#define D_IN   768
#define D_SAE  12288
#define T_LEN  64
#define KTOP   64
#define BATCH  32
#define NROWS  (BATCH * T_LEN)   // 2048

// ---------------- scratch (static device globals; no allocations) ----------------
__device__ __align__(16) float g_pre[(size_t)NROWS * D_SAE];     // 96 MB (exact fp32)
__device__ float g_gate[D_SAE];
__device__ int   g_topidx[NROWS * 128];   // SORTED by composite desc
__device__ float g_topval[NROWS * 128];
__device__ int   g_zidx[NROWS * KTOP];
__device__ float g_zval[NROWS * KTOP];
__device__ float g_rowloss[NROWS];
__device__ unsigned int g_done;           // decode completion counter (reset by last CTA)

// ---------------- helpers ----------------
__device__ __forceinline__ unsigned long long pack2(float x, float y) {
    unsigned long long r;
    asm("mov.b64 %0, {%1, %2};" : "=l"(r) : "f"(x), "f"(y));
    return r;
}
__device__ __forceinline__ float2 unpack2(unsigned long long v) {
    float2 f;
    asm("mov.b64 {%0, %1}, %2;" : "=f"(f.x), "=f"(f.y) : "l"(v));
    return f;
}
__device__ __forceinline__ void fma2(unsigned long long& c, unsigned long long a, unsigned long long b) {
    asm("fma.rn.f32x2 %0, %1, %2, %0;" : "+l"(c) : "l"(a), "l"(b));
}
__device__ __forceinline__ unsigned int fkey(float v) {
    unsigned int u = __float_as_uint(v);
    return (u & 0x80000000u) ? ~u : (u | 0x80000000u);
}
__device__ __forceinline__ float keyToFloat(unsigned int k) {
    unsigned int u = (k & 0x80000000u) ? (k & 0x7FFFFFFFu) : ~k;
    return __uint_as_float(u);
}
// larger == (greater value) or (equal value, smaller index)  [jax top_k tie rule]
__device__ __forceinline__ unsigned long long makeComp(float v, int idx) {
    return ((unsigned long long)fkey(v) << 32) | (unsigned long long)(0xFFFFFFFFu - (unsigned int)idx);
}

// ======================================================================
// Kernel A: fp32 GEMM (proven variant; at the FFMA2 rt=3 roofline).
// ======================================================================
__global__ __launch_bounds__(256, 1) void gemm_enc(const float* __restrict__ X,
                                                   const float* __restrict__ W,
                                                   const float* __restrict__ bias) {
    __shared__ __align__(16) float As[2][16][128];
    __shared__ __align__(16) float Bs[2][16][128];

    const int tid  = threadIdx.x;
    const int row0 = blockIdx.y * 128;
    const int col0 = blockIdx.x * 128;
    const int tx = tid & 15, ty = tid >> 4;

    const int aRow = tid >> 2;
    const int aCol = (tid & 3) * 4;
    const int bRow = tid >> 5;
    const int bCol = (tid & 31) * 4;

    const float* Aptr = X + (size_t)row0 * D_IN;
    const float* Bptr = W + col0;

    float4 a0, a1, b0, b1;
    a0 = *(const float4*)(Aptr + (size_t)aRow * D_IN + aCol);
    a1 = *(const float4*)(Aptr + (size_t)(aRow + 64) * D_IN + aCol);
    b0 = *(const float4*)(Bptr + (size_t)bRow * D_SAE + bCol);
    b1 = *(const float4*)(Bptr + (size_t)(bRow + 8) * D_SAE + bCol);
    As[0][aCol + 0][aRow] = a0.x; As[0][aCol + 1][aRow] = a0.y;
    As[0][aCol + 2][aRow] = a0.z; As[0][aCol + 3][aRow] = a0.w;
    As[0][aCol + 0][aRow + 64] = a1.x; As[0][aCol + 1][aRow + 64] = a1.y;
    As[0][aCol + 2][aRow + 64] = a1.z; As[0][aCol + 3][aRow + 64] = a1.w;
    *(float4*)&Bs[0][bRow][bCol]     = b0;
    *(float4*)&Bs[0][bRow + 8][bCol] = b1;
    __syncthreads();

    unsigned long long cc[4][8];
#pragma unroll
    for (int i = 0; i < 4; ++i)
#pragma unroll
        for (int j = 0; j < 8; ++j) cc[i][j] = 0ull;

    const int NKT = D_IN / 16;  // 48
    for (int kt = 0; kt < NKT; ++kt) {
        const int cur = kt & 1;
        if (kt < NKT - 1) {
            const int k0 = (kt + 1) * 16;
            a0 = *(const float4*)(Aptr + (size_t)aRow * D_IN + k0 + aCol);
            a1 = *(const float4*)(Aptr + (size_t)(aRow + 64) * D_IN + k0 + aCol);
            b0 = *(const float4*)(Bptr + (size_t)(k0 + bRow) * D_SAE + bCol);
            b1 = *(const float4*)(Bptr + (size_t)(k0 + bRow + 8) * D_SAE + bCol);
        }
#pragma unroll
        for (int k = 0; k < 16; ++k) {
            ulonglong2 aa01 = *(const ulonglong2*)&As[cur][k][ty * 4];
            ulonglong2 aa23 = *(const ulonglong2*)&As[cur][k][64 + ty * 4];
            float4 bv0 = *(const float4*)&Bs[cur][k][tx * 4];
            float4 bv1 = *(const float4*)&Bs[cur][k][64 + tx * 4];
            unsigned long long av[4] = {aa01.x, aa01.y, aa23.x, aa23.y};
            unsigned long long bb[8] = {pack2(bv0.x, bv0.x), pack2(bv0.y, bv0.y),
                                        pack2(bv0.z, bv0.z), pack2(bv0.w, bv0.w),
                                        pack2(bv1.x, bv1.x), pack2(bv1.y, bv1.y),
                                        pack2(bv1.z, bv1.z), pack2(bv1.w, bv1.w)};
#pragma unroll
            for (int i = 0; i < 4; ++i)
#pragma unroll
                for (int j = 0; j < 8; ++j) fma2(cc[i][j], av[i], bb[j]);
        }
        if (kt < NKT - 1) {
            const int nxt = cur ^ 1;
            As[nxt][aCol + 0][aRow] = a0.x; As[nxt][aCol + 1][aRow] = a0.y;
            As[nxt][aCol + 2][aRow] = a0.z; As[nxt][aCol + 3][aRow] = a0.w;
            As[nxt][aCol + 0][aRow + 64] = a1.x; As[nxt][aCol + 1][aRow + 64] = a1.y;
            As[nxt][aCol + 2][aRow + 64] = a1.z; As[nxt][aCol + 3][aRow + 64] = a1.w;
            *(float4*)&Bs[nxt][bRow][bCol]     = b0;
            *(float4*)&Bs[nxt][bRow + 8][bCol] = b1;
        }
        __syncthreads();
    }

    float bc[8];
#pragma unroll
    for (int j = 0; j < 8; ++j) bc[j] = bias[col0 + (j >> 2) * 64 + tx * 4 + (j & 3)];

#pragma unroll
    for (int i = 0; i < 4; ++i) {
        const int m = (i >> 1) * 64 + ty * 4 + (i & 1) * 2;
        float2 v[8];
#pragma unroll
        for (int j = 0; j < 8; ++j) v[j] = unpack2(cc[i][j]);
        size_t base = (size_t)(row0 + m) * D_SAE + col0;
        float4 o;
        o.x = v[0].x + bc[0]; o.y = v[1].x + bc[1]; o.z = v[2].x + bc[2]; o.w = v[3].x + bc[3];
        *(float4*)&g_pre[base + tx * 4] = o;
        o.x = v[4].x + bc[4]; o.y = v[5].x + bc[5]; o.z = v[6].x + bc[6]; o.w = v[7].x + bc[7];
        *(float4*)&g_pre[base + 64 + tx * 4] = o;
        base += D_SAE;
        o.x = v[0].y + bc[0]; o.y = v[1].y + bc[1]; o.z = v[2].y + bc[2]; o.w = v[3].y + bc[3];
        *(float4*)&g_pre[base + tx * 4] = o;
        o.x = v[4].y + bc[4]; o.y = v[5].y + bc[5]; o.z = v[6].y + bc[6]; o.w = v[7].y + bc[7];
        *(float4*)&g_pre[base + 64 + tx * 4] = o;
    }
}

// ======================================================================
// Kernel B: exact top-128 per row via threshold-from-maxes (no histogram).
// Blocks 0..47 also fill the gate table (runs before scan launch).
// ======================================================================
#define TK_CAP 4096
__global__ __launch_bounds__(256, 2) void topk128(const float* __restrict__ gate_raw) {
    __shared__ __align__(16) float sMax[256];
    __shared__ __align__(16) unsigned long long cand[TK_CAP + 8];
    __shared__ unsigned int sTkey;
    __shared__ int sCount;

    const int row = blockIdx.x, tid = threadIdx.x, lane = tid & 31;
    const float* rp = g_pre + (size_t)row * D_SAE;

    // fused gate table (48 blocks x 256 = 12288 entries)
    if (row < D_SAE / 256) {
        const int gi = row * 256 + tid;
        g_gate[gi] = 1.0f / (1.0f + expf(-gate_raw[gi]));
    }

    float v[48];
#pragma unroll
    for (int i = 0; i < 12; ++i) {
        const float4 q = *(const float4*)(rp + (size_t)(tid + i * 256) * 4);
        v[i * 4 + 0] = q.x; v[i * 4 + 1] = q.y; v[i * 4 + 2] = q.z; v[i * 4 + 3] = q.w;
    }
    float m = v[0];
#pragma unroll
    for (int i = 1; i < 48; ++i) m = fmaxf(m, v[i]);
    sMax[tid] = m;
    if (tid == 0) { sTkey = 0xFFFFFFFFu; sCount = 0; }
    __syncthreads();

    {
        const unsigned int mk = fkey(m);
        int r = 0;
#pragma unroll
        for (int j = 0; j < 256; j += 4) {
            const float4 q = *(const float4*)&sMax[j];
            r += (fkey(q.x) > mk) + (fkey(q.y) > mk) + (fkey(q.z) > mk) + (fkey(q.w) > mk);
        }
        if (r <= 127) atomicMin(&sTkey, mk);
    }
    __syncthreads();
    const unsigned int T = sTkey;

#pragma unroll
    for (int i = 0; i < 48; ++i) {
        const int flag = (fkey(v[i]) >= T);
        const unsigned bal = __ballot_sync(0xFFFFFFFFu, flag);
        if (bal) {
            int base = 0;
            if (lane == 0) base = atomicAdd(&sCount, __popc(bal));
            base = __shfl_sync(0xFFFFFFFFu, base, 0);
            if (flag) {
                const int pos = base + __popc(bal & ((1u << lane) - 1));
                if (pos < TK_CAP) {
                    const int idx = (tid + (i >> 2) * 256) * 4 + (i & 3);
                    cand[pos] = makeComp(v[i], idx);
                }
            }
        }
    }
    __syncthreads();

    const int nc = min(sCount, TK_CAP);
    if (tid < 8) cand[nc + tid] = 0ull;
    __syncthreads();

    for (int c = tid; c < nc; c += 256) {
        const unsigned long long me = cand[c];
        int r = 0;
        for (int j = 0; j < nc; j += 8) {
            const ulonglong2 c0 = *(const ulonglong2*)&cand[j];
            const ulonglong2 c1 = *(const ulonglong2*)&cand[j + 2];
            const ulonglong2 c2 = *(const ulonglong2*)&cand[j + 4];
            const ulonglong2 c3 = *(const ulonglong2*)&cand[j + 6];
            r += (c0.x > me) + (c0.y > me) + (c1.x > me) + (c1.y > me)
               + (c2.x > me) + (c2.y > me) + (c3.x > me) + (c3.y > me);
        }
        if (r < 128) {
            g_topidx[row * 128 + r] = (int)(0xFFFFFFFFu - (unsigned int)me);
            g_topval[row * 128 + r] = keyToFloat((unsigned int)(me >> 32));
        }
    }
}

// ======================================================================
// Kernel C: scan (R14 measured-best; frozen).
// ======================================================================
__global__ __launch_bounds__(128) void scan_kernel(float* __restrict__ z_last) {
    __shared__ unsigned int bitmap[D_SAE / 32];
    __shared__ __align__(16) unsigned long long cand[128];
    __shared__ int tmpIdx[KTOP];
    __shared__ float tmpVal[KTOP];
    __shared__ int warpCnt[4];

    const int b = blockIdx.x, tid = threadIdx.x, lane = tid & 31, w = tid >> 5;
    const int row0 = b * T_LEN;

    for (int i = tid; i < D_SAE; i += 128) z_last[(size_t)b * D_SAE + i] = 0.0f;
    for (int i = tid; i < D_SAE / 32; i += 128) bitmap[i] = 0;

    int   pIdx = 0;
    float pVal = 0.0f;
    int nprev = 0;

    int   nIdx = g_topidx[(size_t)row0 * 128 + tid];
    float nVal = g_topval[(size_t)row0 * 128 + tid];
    __syncthreads();

    for (int t = 0; t < T_LEN; ++t) {
        const int row = row0 + t;

        float preV = 0.0f, gV = 0.0f;
        if (tid < nprev) {
            preV = g_pre[(size_t)row * D_SAE + pIdx];
            gV   = g_gate[pIdx];
        }
        int nIdx2 = 0; float nVal2 = 0.0f;
        if (t + 1 < T_LEN) {
            nIdx2 = g_topidx[(size_t)(row + 1) * 128 + tid];
            nVal2 = g_topval[(size_t)(row + 1) * 128 + tid];
        }

        const int flag = !((bitmap[nIdx >> 5] >> (nIdx & 31)) & 1u);
        const unsigned bal = __ballot_sync(0xFFFFFFFFu, flag);
        if (lane == 0) warpCnt[w] = __popc(bal);
        __syncthreads();   // S1

        int off = __popc(bal & ((1u << lane) - 1));
#pragma unroll
        for (int q = 0; q < 4; ++q) off += (q < w) ? warpCnt[q] : 0;
        const int tn = min(warpCnt[0] + warpCnt[1] + warpCnt[2] + warpCnt[3], KTOP);
        if (flag && off < KTOP) cand[64 + off] = makeComp(nVal, nIdx);
        if (tid >= tn && tid < 64) cand[64 + tid] = 0ull;
        if (tid < 64)
            cand[tid] = (tid < nprev) ? makeComp(gV * pVal + preV, pIdx) : 0ull;
        if (tid < nprev) atomicAnd(&bitmap[pIdx >> 5], ~(1u << (pIdx & 31)));
        __syncthreads();   // S2

        {
            const unsigned long long me = cand[tid];
            int r0 = 0, r1 = 0;
#pragma unroll
            for (int j = 0; j < 128; j += 16) {
                const ulonglong2 c0 = *(const ulonglong2*)&cand[j];
                const ulonglong2 c1 = *(const ulonglong2*)&cand[j + 2];
                const ulonglong2 c2 = *(const ulonglong2*)&cand[j + 4];
                const ulonglong2 c3 = *(const ulonglong2*)&cand[j + 6];
                const ulonglong2 c4 = *(const ulonglong2*)&cand[j + 8];
                const ulonglong2 c5 = *(const ulonglong2*)&cand[j + 10];
                const ulonglong2 c6 = *(const ulonglong2*)&cand[j + 12];
                const ulonglong2 c7 = *(const ulonglong2*)&cand[j + 14];
                r0 += (c0.x > me) + (c0.y > me) + (c1.x > me) + (c1.y > me)
                    + (c2.x > me) + (c2.y > me) + (c3.x > me) + (c3.y > me);
                r1 += (c4.x > me) + (c4.y > me) + (c5.x > me) + (c5.y > me)
                    + (c6.x > me) + (c6.y > me) + (c7.x > me) + (c7.y > me);
            }
            const int r = r0 + r1;
            if (me != 0ull && r < KTOP) {
                tmpIdx[r] = (int)(0xFFFFFFFFu - (unsigned int)me);
                tmpVal[r] = fmaxf(keyToFloat((unsigned int)(me >> 32)), 0.0f);
            }
        }
        __syncthreads();   // S3

        if (tid < KTOP) {
            pIdx = tmpIdx[tid];
            pVal = tmpVal[tid];
            atomicOr(&bitmap[pIdx >> 5], 1u << (pIdx & 31));
            g_zidx[row * KTOP + tid] = pIdx;
            g_zval[row * KTOP + tid] = pVal;
            if (t == T_LEN - 1) z_last[(size_t)b * D_SAE + pIdx] = pVal;
        }
        nprev = KTOP;
        nIdx = nIdx2; nVal = nVal2;
        __syncthreads();   // S4
    }
}

// ======================================================================
// Kernel D: sparse decode + per-row squared error + fused final loss.
// Last-finishing CTA (deterministic fixed-order reduction) writes loss.
// ======================================================================
__global__ __launch_bounds__(192) void decode_kernel(const float* __restrict__ X,
                                                     const float* __restrict__ Wd,
                                                     const float* __restrict__ b_dec,
                                                     float* __restrict__ xhat,
                                                     float* __restrict__ out_loss) {
    __shared__ int sIdx[KTOP];
    __shared__ float sVal[KTOP];
    __shared__ float red[192];
    __shared__ unsigned int sLast;
    const int row = blockIdx.x, tid = threadIdx.x;
    if (tid < KTOP) {
        sIdx[tid] = g_zidx[row * KTOP + tid];
        sVal[tid] = g_zval[row * KTOP + tid];
    }
    __syncthreads();

    float4 acc = *(const float4*)(b_dec + tid * 4);
#pragma unroll 4
    for (int k = 0; k < KTOP; ++k) {
        const float v = sVal[k];
        const float4 wv = *(const float4*)(Wd + (size_t)sIdx[k] * D_IN + tid * 4);
        acc.x += v * wv.x; acc.y += v * wv.y; acc.z += v * wv.z; acc.w += v * wv.w;
    }
    float* op = xhat + (size_t)row * D_IN + tid * 4;
    op[0] = acc.x; op[1] = acc.y; op[2] = acc.z; op[3] = acc.w;

    const float4 xv = *(const float4*)(X + (size_t)row * D_IN + tid * 4);
    const float dx = acc.x - xv.x, dy = acc.y - xv.y, dz = acc.z - xv.z, dw = acc.w - xv.w;
    red[tid] = dx * dx + dy * dy + dz * dz + dw * dw;
    __syncthreads();
    for (int s = 96; s >= 6; s >>= 1) {
        if (tid < s) red[tid] += red[tid + s];
        __syncthreads();
    }
    if (tid == 0) {
        float total = 0.f;
        for (int i = 0; i < 6; ++i) total += red[i];
        g_rowloss[row] = total;
        __threadfence();
        sLast = atomicAdd(&g_done, 1u);
    }
    __syncthreads();

    // last CTA: fixed-order deterministic reduction of all 2048 row losses
    if (sLast == (unsigned int)(NROWS - 1)) {
        if (tid == 0) g_done = 0;   // reset for next graph replay
        float acc2 = 0.0f;
        // fixed serial order per thread: rows tid, tid+192, ...
        for (int i = tid; i < NROWS; i += 192) acc2 += g_rowloss[i];
        red[tid] = acc2;
        __syncthreads();
        for (int s = 96; s >= 6; s >>= 1) {
            if (tid < s) red[tid] += red[tid + s];
            __syncthreads();
        }
        if (tid == 0) {
            float total = 0.f;
            for (int i = 0; i < 6; ++i) total += red[i];
            out_loss[0] = total / (float)NROWS;
        }
    }
}

// ======================================================================
extern "C" void kernel_launch(void* const* d_in, const int* in_sizes, int n_in,
                              void* d_out, int out_size) {
    const float* x        = (const float*)d_in[0];
    const float* W_enc    = (const float*)d_in[1];
    const float* W_dec    = (const float*)d_in[2];
    const float* b_enc    = (const float*)d_in[3];
    const float* b_dec    = (const float*)d_in[4];
    const float* gate_raw = (const float*)d_in[5];

    float* out       = (float*)d_out;
    float* out_loss  = out;
    float* out_xhat  = out + 1;
    float* out_zlast = out + 1 + (size_t)NROWS * D_IN;

    dim3 gGrid(D_SAE / 128, NROWS / 128);  // (96, 16)
    gemm_enc<<<gGrid, 256>>>(x, W_enc, b_enc);
    topk128<<<NROWS, 256>>>(gate_raw);
    scan_kernel<<<BATCH, 128>>>(out_zlast);
    decode_kernel<<<NROWS, 192>>>(x, W_dec, b_dec, out_xhat, out_loss);
}